// round 1
// baseline (speedup 1.0000x reference)
#include <cuda_runtime.h>

#define BB 16
#define TT 24
#define HH 96
#define WW 96
#define CINc 16
#define FFc 16
#define COc 64
#define TILE_W 32
#define TILE_H 16
#define SWc 34
#define SHc 18
#define PLANE (SWc*SHc)   // 612

// ping-pong state buffers (NHWC, B*96*96*16 floats each)
__device__ float g_h[2][BB*HH*WW*FFc];
__device__ float g_c[2][BB*HH*WW*FFc];

__device__ __forceinline__ unsigned long long pack2(float lo, float hi) {
    unsigned long long r;
    asm("mov.b64 %0, {%1, %2};" : "=l"(r) : "f"(lo), "f"(hi));
    return r;
}
__device__ __forceinline__ void unpack2(unsigned long long v, float &lo, float &hi) {
    asm("mov.b64 {%0, %1}, %2;" : "=f"(lo), "=f"(hi) : "l"(v));
}
// packed dual-fp32 FMA (Blackwell FFMA2 — only reachable via PTX fma.rn.f32x2)
__device__ __forceinline__ void ffma2(unsigned long long &acc,
                                      unsigned long long a,
                                      unsigned long long b) {
    asm("fma.rn.f32x2 %0, %1, %2, %0;" : "+l"(acc) : "l"(a), "l"(b));
}

__device__ __forceinline__ float sigmoidf_(float x) {
    return 1.0f / (1.0f + __expf(-x));
}

// smem layout (floats): wx[9216] wh[9216] bias[64] xtile[16*612] htile[16*612]
#define S_WX  0
#define S_WH  9216
#define S_B   18432
#define S_X   18496
#define S_H   (18496 + 16*PLANE)
#define SMEM_FLOATS (18496 + 32*PLANE)

template<bool FIRST, bool LAST>
__global__ __launch_bounds__(512, 1)
void convlstm_step(const float* __restrict__ x_all,
                   const float* __restrict__ wk,
                   const float* __restrict__ wr,
                   const float* __restrict__ bias,
                   const float* __restrict__ dense_w,
                   const float* __restrict__ dense_b,
                   float* __restrict__ out,
                   int t, int rd, int wi)
{
    extern __shared__ float smem[];
    float* s_wx = smem + S_WX;
    float* s_wh = smem + S_WH;
    float* s_b  = smem + S_B;
    float* s_x  = smem + S_X;
    float* s_h  = smem + S_H;

    const int tid = threadIdx.x;
    const int b   = blockIdx.z;
    const int by0 = blockIdx.y * TILE_H;
    const int bx0 = blockIdx.x * TILE_W;

    // ---- stage weights + bias into smem (same linear layout as HWIO global) ----
    {
        const float4* src = (const float4*)wk;
        float4* dst = (float4*)s_wx;
        for (int i = tid; i < 2304; i += 512) dst[i] = src[i];
        src = (const float4*)wr;
        dst = (float4*)s_wh;
        for (int i = tid; i < 2304; i += 512) dst[i] = src[i];
        if (tid < 16) ((float4*)s_b)[tid] = ((const float4*)bias)[tid];
    }

    // ---- stage x and h halo tiles, planar [cin][sy][sx] layout ----
    const float* x_t  = x_all + ((size_t)(b * TT + t)) * (HH * WW * CINc);
    const float* h_in = g_h[rd] + (size_t)b * (HH * WW * FFc);

    for (int p = tid; p < PLANE; p += 512) {
        const int sy = p / SWc, sx = p - sy * SWc;
        const int gy = by0 + sy - 1, gx = bx0 + sx - 1;
        const bool ok = (gy >= 0) & (gy < HH) & (gx >= 0) & (gx < WW);
        const int base = (gy * WW + gx) * CINc;
        #pragma unroll
        for (int c4 = 0; c4 < 4; ++c4) {
            float4 xv = ok ? ((const float4*)(x_t + base))[c4]
                           : make_float4(0.f, 0.f, 0.f, 0.f);
            const int cb = c4 * 4;
            s_x[(cb + 0) * PLANE + p] = xv.x;
            s_x[(cb + 1) * PLANE + p] = xv.y;
            s_x[(cb + 2) * PLANE + p] = xv.z;
            s_x[(cb + 3) * PLANE + p] = xv.w;
            if (!FIRST) {
                float4 hv = ok ? ((const float4*)(h_in + base))[c4]
                               : make_float4(0.f, 0.f, 0.f, 0.f);
                s_h[(cb + 0) * PLANE + p] = hv.x;
                s_h[(cb + 1) * PLANE + p] = hv.y;
                s_h[(cb + 2) * PLANE + p] = hv.z;
                s_h[(cb + 3) * PLANE + p] = hv.w;
            }
        }
    }
    __syncthreads();

    const int tx = tid & 31;
    const int ty = tid >> 5;

    // ---- 64 gate pre-activations as 32 packed f32x2 accumulators ----
    unsigned long long acc[32];
    #pragma unroll
    for (int j = 0; j < 32; ++j) {
        float2 b2 = ((const float2*)s_b)[j];
        acc[j] = pack2(b2.x, b2.y);
    }

    #pragma unroll 1
    for (int cin = 0; cin < CINc; ++cin) {
        const float* xp = s_x + cin * PLANE + ty * SWc + tx;
        const float* hp = s_h + cin * PLANE + ty * SWc + tx;
        #pragma unroll
        for (int dy = 0; dy < 3; ++dy) {
            #pragma unroll
            for (int dx = 0; dx < 3; ++dx) {
                const int tap = dy * 3 + dx;
                const float xa = xp[dy * SWc + dx];
                const unsigned long long a2 = pack2(xa, xa);
                const ulonglong2* wq =
                    (const ulonglong2*)(s_wx + (tap * CINc + cin) * COc);
                #pragma unroll
                for (int q = 0; q < 16; ++q) {
                    ulonglong2 wv = wq[q];
                    ffma2(acc[2 * q],     a2, wv.x);
                    ffma2(acc[2 * q + 1], a2, wv.y);
                }
                if (!FIRST) {
                    const float ha = hp[dy * SWc + dx];
                    const unsigned long long h2 = pack2(ha, ha);
                    const ulonglong2* uq =
                        (const ulonglong2*)(s_wh + (tap * CINc + cin) * COc);
                    #pragma unroll
                    for (int q = 0; q < 16; ++q) {
                        ulonglong2 wv = uq[q];
                        ffma2(acc[2 * q],     h2, wv.x);
                        ffma2(acc[2 * q + 1], h2, wv.y);
                    }
                }
            }
        }
    }

    // ---- gate epilogue ----
    float z[64];
    #pragma unroll
    for (int j = 0; j < 32; ++j) unpack2(acc[j], z[2 * j], z[2 * j + 1]);

    const int gy = by0 + ty;
    const int gx = bx0 + tx;
    const size_t pix = ((size_t)b * (HH * WW) + gy * WW + gx) * FFc;

    float cprev[16];
    if (!FIRST) {
        #pragma unroll
        for (int q = 0; q < 4; ++q)
            ((float4*)cprev)[q] = ((const float4*)(g_c[rd] + pix))[q];
    }

    float hn[16], cn[16];
    #pragma unroll
    for (int k = 0; k < 16; ++k) {
        const float ig = sigmoidf_(z[k]);
        const float fg = sigmoidf_(z[16 + k]);
        const float zc = z[32 + k];
        const float og = sigmoidf_(z[48 + k]);
        const float cp = FIRST ? 0.f : cprev[k];
        const float c  = fg * cp + ig * fmaxf(zc, 0.f);
        cn[k] = c;
        hn[k] = og * fmaxf(c, 0.f);
    }

    if (!LAST) {
        #pragma unroll
        for (int q = 0; q < 4; ++q) {
            ((float4*)(g_c[wi] + pix))[q] = ((const float4*)cn)[q];
            ((float4*)(g_h[wi] + pix))[q] = ((const float4*)hn)[q];
        }
    } else {
        // fused Dense(16 -> 1)
        float s = dense_b[0];
        #pragma unroll
        for (int k = 0; k < 16; ++k) s += hn[k] * dense_w[k];
        out[(size_t)b * (HH * WW) + gy * WW + gx] = s;
    }
}

extern "C" void kernel_launch(void* const* d_in, const int* in_sizes, int n_in,
                              void* d_out, int out_size)
{
    const float* x    = (const float*)d_in[0];
    const float* wk   = (const float*)d_in[1];
    const float* wr   = (const float*)d_in[2];
    const float* bias = (const float*)d_in[3];
    const float* dw   = (const float*)d_in[4];
    const float* db   = (const float*)d_in[5];
    float* out = (float*)d_out;

    const int smem_bytes = SMEM_FLOATS * 4;  // 149 KB
    cudaFuncSetAttribute(convlstm_step<true,  false>,
                         cudaFuncAttributeMaxDynamicSharedMemorySize, smem_bytes);
    cudaFuncSetAttribute(convlstm_step<false, false>,
                         cudaFuncAttributeMaxDynamicSharedMemorySize, smem_bytes);
    cudaFuncSetAttribute(convlstm_step<false, true>,
                         cudaFuncAttributeMaxDynamicSharedMemorySize, smem_bytes);

    dim3 grid(WW / TILE_W, HH / TILE_H, BB);   // (3, 6, 16) = 288 blocks
    dim3 block(512);

    for (int t = 0; t < TT; ++t) {
        const int rd = (t + 1) & 1;   // read buffer
        const int wi = t & 1;         // write buffer
        if (t == 0) {
            convlstm_step<true, false><<<grid, block, smem_bytes>>>(
                x, wk, wr, bias, dw, db, out, t, rd, wi);
        } else if (t == TT - 1) {
            convlstm_step<false, true><<<grid, block, smem_bytes>>>(
                x, wk, wr, bias, dw, db, out, t, rd, wi);
        } else {
            convlstm_step<false, false><<<grid, block, smem_bytes>>>(
                x, wk, wr, bias, dw, db, out, t, rd, wi);
        }
    }
}

// round 9
// speedup vs baseline: 1.6939x; 1.6939x over previous
#include <cuda_runtime.h>

#define BB 16
#define TT 24
#define HH 96
#define WW 96
#define CINc 16
#define FFc 16
#define COc 64
#define TILE_W 32
#define TILE_H 16
#define SWc 36           // padded row (34 used) for float4 alignment
#define SHc 18
#define PLANE (SWc*SHc)  // 648

// ping-pong state buffers (NHWC, B*96*96*16 floats each)
__device__ float g_h[2][BB*HH*WW*FFc];
__device__ float g_c[2][BB*HH*WW*FFc];

__device__ __forceinline__ unsigned long long pack2(float lo, float hi) {
    unsigned long long r;
    asm("mov.b64 %0, {%1, %2};" : "=l"(r) : "f"(lo), "f"(hi));
    return r;
}
__device__ __forceinline__ void unpack2(unsigned long long v, float &lo, float &hi) {
    asm("mov.b64 {%0, %1}, %2;" : "=f"(lo), "=f"(hi) : "l"(v));
}
// packed dual-fp32 FMA (Blackwell FFMA2 — only reachable via PTX fma.rn.f32x2)
__device__ __forceinline__ void ffma2(unsigned long long &acc,
                                      unsigned long long a,
                                      unsigned long long b) {
    asm("fma.rn.f32x2 %0, %1, %2, %0;" : "+l"(acc) : "l"(a), "l"(b));
}

__device__ __forceinline__ float sigmoidf_(float x) {
    return 1.0f / (1.0f + __expf(-x));
}

// smem layout (floats)
#define S_WX  0
#define S_WH  9216
#define S_B   18432
#define S_X   18496
#define S_H   (18496 + 16*PLANE)           // 28864
#define SMEM_FLOATS (18496 + 32*PLANE)     // 39232 floats = 156928 B

template<bool FIRST, bool LAST>
__global__ __launch_bounds__(512, 1)
void convlstm_step(const float* __restrict__ x_all,
                   const float* __restrict__ wk,
                   const float* __restrict__ wr,
                   const float* __restrict__ bias,
                   const float* __restrict__ dense_w,
                   const float* __restrict__ dense_b,
                   float* __restrict__ out,
                   int t, int rd, int wi)
{
    extern __shared__ float smem[];
    float* s_wx = smem + S_WX;
    float* s_wh = smem + S_WH;
    float* s_b  = smem + S_B;
    float* s_x  = smem + S_X;
    float* s_h  = smem + S_H;

    const int tid = threadIdx.x;
    const int b   = blockIdx.z;
    const int by0 = blockIdx.y * TILE_H;
    const int bx0 = blockIdx.x * TILE_W;

    // ---- stage weights + bias into smem (same linear layout as HWIO global) ----
    {
        const float4* src = (const float4*)wk;
        float4* dst = (float4*)s_wx;
        for (int i = tid; i < 2304; i += 512) dst[i] = src[i];
        src = (const float4*)wr;
        dst = (float4*)s_wh;
        for (int i = tid; i < 2304; i += 512) dst[i] = src[i];
        if (tid < 16) ((float4*)s_b)[tid] = ((const float4*)bias)[tid];
    }

    // ---- stage x and h halo tiles, planar [cin][sy(18)][sx(36 padded)] ----
    const float* x_t  = x_all + ((size_t)(b * TT + t)) * (HH * WW * CINc);
    const float* h_in = g_h[rd] + (size_t)b * (HH * WW * FFc);

    for (int p = tid; p < 34 * 18; p += 512) {
        const int sy = p / 34, sx = p - sy * 34;
        const int idx = sy * SWc + sx;
        const int gy = by0 + sy - 1, gx = bx0 + sx - 1;
        const bool ok = (gy >= 0) & (gy < HH) & (gx >= 0) & (gx < WW);
        const int base = (gy * WW + gx) * CINc;
        #pragma unroll
        for (int c4 = 0; c4 < 4; ++c4) {
            float4 xv = ok ? ((const float4*)(x_t + base))[c4]
                           : make_float4(0.f, 0.f, 0.f, 0.f);
            const int cb = c4 * 4;
            s_x[(cb + 0) * PLANE + idx] = xv.x;
            s_x[(cb + 1) * PLANE + idx] = xv.y;
            s_x[(cb + 2) * PLANE + idx] = xv.z;
            s_x[(cb + 3) * PLANE + idx] = xv.w;
            if (!FIRST) {
                float4 hv = ok ? ((const float4*)(h_in + base))[c4]
                               : make_float4(0.f, 0.f, 0.f, 0.f);
                s_h[(cb + 0) * PLANE + idx] = hv.x;
                s_h[(cb + 1) * PLANE + idx] = hv.y;
                s_h[(cb + 2) * PLANE + idx] = hv.z;
                s_h[(cb + 3) * PLANE + idx] = hv.w;
            }
        }
    }
    __syncthreads();

    // ---- thread mapping: 4 pixels x 16 couts per thread ----
    const int g   = tid & 3;         // channel group: couts {16*gate + 4g + 0..3}
    const int pg  = tid >> 2;        // pixel group 0..127
    const int ty  = pg >> 3;         // 0..15
    const int tx0 = (pg & 7) * 4;    // 0,4,...,28

    // acc[px][j], j = gate*2 + pair; covers couts 16*gate + 4g + 2*pair + {0,1}
    unsigned long long acc[4][8];
    #pragma unroll
    for (int gate = 0; gate < 4; ++gate) {
        #pragma unroll
        for (int pr = 0; pr < 2; ++pr) {
            float2 b2 = *(const float2*)(s_b + gate * 16 + 4 * g + 2 * pr);
            unsigned long long bv = pack2(b2.x, b2.y);
            #pragma unroll
            for (int px = 0; px < 4; ++px) acc[px][gate * 2 + pr] = bv;
        }
    }

    #pragma unroll 1
    for (int cin = 0; cin < CINc; ++cin) {
        const float* xp = s_x + cin * PLANE + ty * SWc + tx0;
        const float* hp = s_h + cin * PLANE + ty * SWc + tx0;
        #pragma unroll
        for (int dy = 0; dy < 3; ++dy) {
            float xr[6], hr[6];
            {
                float4 v4 = *(const float4*)(xp + dy * SWc);
                float2 v2 = *(const float2*)(xp + dy * SWc + 4);
                xr[0] = v4.x; xr[1] = v4.y; xr[2] = v4.z; xr[3] = v4.w;
                xr[4] = v2.x; xr[5] = v2.y;
                if (!FIRST) {
                    float4 w4 = *(const float4*)(hp + dy * SWc);
                    float2 w2 = *(const float2*)(hp + dy * SWc + 4);
                    hr[0] = w4.x; hr[1] = w4.y; hr[2] = w4.z; hr[3] = w4.w;
                    hr[4] = w2.x; hr[5] = w2.y;
                }
            }
            #pragma unroll
            for (int dx = 0; dx < 3; ++dx) {
                const int tap = dy * 3 + dx;
                // x weights: 16 couts for this thread = 4 x LDS.128
                {
                    const float* wb = s_wx + (tap * CINc + cin) * COc + 4 * g;
                    unsigned long long w[8];
                    #pragma unroll
                    for (int gate = 0; gate < 4; ++gate) {
                        ulonglong2 wv = *(const ulonglong2*)(wb + gate * 16);
                        w[gate * 2]     = wv.x;
                        w[gate * 2 + 1] = wv.y;
                    }
                    #pragma unroll
                    for (int px = 0; px < 4; ++px) {
                        const float a = xr[dx + px];
                        const unsigned long long a2 = pack2(a, a);
                        #pragma unroll
                        for (int j = 0; j < 8; ++j) ffma2(acc[px][j], a2, w[j]);
                    }
                }
                if (!FIRST) {
                    const float* wb = s_wh + (tap * CINc + cin) * COc + 4 * g;
                    unsigned long long w[8];
                    #pragma unroll
                    for (int gate = 0; gate < 4; ++gate) {
                        ulonglong2 wv = *(const ulonglong2*)(wb + gate * 16);
                        w[gate * 2]     = wv.x;
                        w[gate * 2 + 1] = wv.y;
                    }
                    #pragma unroll
                    for (int px = 0; px < 4; ++px) {
                        const float a = hr[dx + px];
                        const unsigned long long a2 = pack2(a, a);
                        #pragma unroll
                        for (int j = 0; j < 8; ++j) ffma2(acc[px][j], a2, w[j]);
                    }
                }
            }
        }
    }

    // ---- gate epilogue, per pixel, 4 filters per thread ----
    const int gy = by0 + ty;
    #pragma unroll
    for (int px = 0; px < 4; ++px) {
        float zv[4][4];  // [gate][filter k 0..3]
        #pragma unroll
        for (int gate = 0; gate < 4; ++gate) {
            unpack2(acc[px][gate * 2],     zv[gate][0], zv[gate][1]);
            unpack2(acc[px][gate * 2 + 1], zv[gate][2], zv[gate][3]);
        }
        const int gx = bx0 + tx0 + px;
        const size_t pix = ((size_t)b * (HH * WW) + gy * WW + gx) * FFc + 4 * g;

        float cprev[4] = {0.f, 0.f, 0.f, 0.f};
        if (!FIRST) *(float4*)cprev = *(const float4*)(g_c[rd] + pix);

        float hn[4], cn[4];
        #pragma unroll
        for (int k = 0; k < 4; ++k) {
            const float ig = sigmoidf_(zv[0][k]);
            const float fg = sigmoidf_(zv[1][k]);
            const float zc = zv[2][k];
            const float og = sigmoidf_(zv[3][k]);
            const float c  = fg * cprev[k] + ig * fmaxf(zc, 0.f);
            cn[k] = c;
            hn[k] = og * fmaxf(c, 0.f);
        }

        if (!LAST) {
            *(float4*)(g_c[wi] + pix) = *(const float4*)cn;
            *(float4*)(g_h[wi] + pix) = *(const float4*)hn;
        } else {
            // fused Dense(16->1): partial over this thread's 4 filters,
            // then 4-lane butterfly reduce (lanes g=0..3 of the pixel group)
            float s = hn[0] * dense_w[4 * g + 0] + hn[1] * dense_w[4 * g + 1]
                    + hn[2] * dense_w[4 * g + 2] + hn[3] * dense_w[4 * g + 3];
            s += __shfl_xor_sync(0xFFFFFFFFu, s, 1);
            s += __shfl_xor_sync(0xFFFFFFFFu, s, 2);
            if (g == 0)
                out[(size_t)b * (HH * WW) + gy * WW + gx] = s + dense_b[0];
        }
    }
}

extern "C" void kernel_launch(void* const* d_in, const int* in_sizes, int n_in,
                              void* d_out, int out_size)
{
    const float* x    = (const float*)d_in[0];
    const float* wk   = (const float*)d_in[1];
    const float* wr   = (const float*)d_in[2];
    const float* bias = (const float*)d_in[3];
    const float* dw   = (const float*)d_in[4];
    const float* db   = (const float*)d_in[5];
    float* out = (float*)d_out;

    const int smem_bytes = SMEM_FLOATS * 4;  // ~153 KB
    cudaFuncSetAttribute(convlstm_step<true,  false>,
                         cudaFuncAttributeMaxDynamicSharedMemorySize, smem_bytes);
    cudaFuncSetAttribute(convlstm_step<false, false>,
                         cudaFuncAttributeMaxDynamicSharedMemorySize, smem_bytes);
    cudaFuncSetAttribute(convlstm_step<false, true>,
                         cudaFuncAttributeMaxDynamicSharedMemorySize, smem_bytes);

    dim3 grid(WW / TILE_W, HH / TILE_H, BB);   // (3, 6, 16) = 288 blocks
    dim3 block(512);

    for (int t = 0; t < TT; ++t) {
        const int rd = (t + 1) & 1;   // read buffer
        const int wi = t & 1;         // write buffer
        if (t == 0) {
            convlstm_step<true, false><<<grid, block, smem_bytes>>>(
                x, wk, wr, bias, dw, db, out, t, rd, wi);
        } else if (t == TT - 1) {
            convlstm_step<false, true><<<grid, block, smem_bytes>>>(
                x, wk, wr, bias, dw, db, out, t, rd, wi);
        } else {
            convlstm_step<false, false><<<grid, block, smem_bytes>>>(
                x, wk, wr, bias, dw, db, out, t, rd, wi);
        }
    }
}

// round 10
// speedup vs baseline: 1.6940x; 1.0001x over previous
#include <cuda_runtime.h>

#define BB 16
#define TT 24
#define HH 96
#define WW 96
#define CINc 16
#define FFc 16
#define COc 64
#define TILE_W 32
#define TILE_H 16
#define SWc 36           // padded row (34 used) for float4 alignment
#define SHc 18
#define PLANE (SWc*SHc)  // 648

// ping-pong state buffers (NHWC, B*96*96*16 floats each)
__device__ float g_h[2][BB*HH*WW*FFc];
__device__ float g_c[2][BB*HH*WW*FFc];

__device__ __forceinline__ unsigned long long pack2(float lo, float hi) {
    unsigned long long r;
    asm("mov.b64 %0, {%1, %2};" : "=l"(r) : "f"(lo), "f"(hi));
    return r;
}
__device__ __forceinline__ void unpack2(unsigned long long v, float &lo, float &hi) {
    asm("mov.b64 {%0, %1}, %2;" : "=f"(lo), "=f"(hi) : "l"(v));
}
// packed dual-fp32 FMA (Blackwell FFMA2 — only reachable via PTX fma.rn.f32x2)
__device__ __forceinline__ void ffma2(unsigned long long &acc,
                                      unsigned long long a,
                                      unsigned long long b) {
    asm("fma.rn.f32x2 %0, %1, %2, %0;" : "+l"(acc) : "l"(a), "l"(b));
}

__device__ __forceinline__ float sigmoidf_(float x) {
    return 1.0f / (1.0f + __expf(-x));
}

// smem layout (floats)
#define S_WX  0
#define S_WH  9216
#define S_B   18432
#define S_X   18496
#define S_H   (18496 + 16*PLANE)           // 28864
#define SMEM_FLOATS (18496 + 32*PLANE)     // 39232 floats = 156928 B

template<bool FIRST, bool LAST>
__global__ __launch_bounds__(512, 1)
void convlstm_step(const float* __restrict__ x_all,
                   const float* __restrict__ wk,
                   const float* __restrict__ wr,
                   const float* __restrict__ bias,
                   const float* __restrict__ dense_w,
                   const float* __restrict__ dense_b,
                   float* __restrict__ out,
                   int t, int rd, int wi)
{
    extern __shared__ float smem[];
    float* s_wx = smem + S_WX;
    float* s_wh = smem + S_WH;
    float* s_b  = smem + S_B;
    float* s_x  = smem + S_X;
    float* s_h  = smem + S_H;

    const int tid = threadIdx.x;
    const int b   = blockIdx.z;
    const int by0 = blockIdx.y * TILE_H;
    const int bx0 = blockIdx.x * TILE_W;

    // ---- stage weights + bias into smem (same linear layout as HWIO global) ----
    {
        const float4* src = (const float4*)wk;
        float4* dst = (float4*)s_wx;
        for (int i = tid; i < 2304; i += 512) dst[i] = src[i];
        src = (const float4*)wr;
        dst = (float4*)s_wh;
        for (int i = tid; i < 2304; i += 512) dst[i] = src[i];
        if (tid < 16) ((float4*)s_b)[tid] = ((const float4*)bias)[tid];
    }

    // ---- stage x and h halo tiles, planar [cin][sy(18)][sx(36 padded)] ----
    const float* x_t  = x_all + ((size_t)(b * TT + t)) * (HH * WW * CINc);
    const float* h_in = g_h[rd] + (size_t)b * (HH * WW * FFc);

    for (int p = tid; p < 34 * 18; p += 512) {
        const int sy = p / 34, sx = p - sy * 34;
        const int idx = sy * SWc + sx;
        const int gy = by0 + sy - 1, gx = bx0 + sx - 1;
        const bool ok = (gy >= 0) & (gy < HH) & (gx >= 0) & (gx < WW);
        const int base = (gy * WW + gx) * CINc;
        #pragma unroll
        for (int c4 = 0; c4 < 4; ++c4) {
            float4 xv = ok ? ((const float4*)(x_t + base))[c4]
                           : make_float4(0.f, 0.f, 0.f, 0.f);
            const int cb = c4 * 4;
            s_x[(cb + 0) * PLANE + idx] = xv.x;
            s_x[(cb + 1) * PLANE + idx] = xv.y;
            s_x[(cb + 2) * PLANE + idx] = xv.z;
            s_x[(cb + 3) * PLANE + idx] = xv.w;
            if (!FIRST) {
                float4 hv = ok ? ((const float4*)(h_in + base))[c4]
                               : make_float4(0.f, 0.f, 0.f, 0.f);
                s_h[(cb + 0) * PLANE + idx] = hv.x;
                s_h[(cb + 1) * PLANE + idx] = hv.y;
                s_h[(cb + 2) * PLANE + idx] = hv.z;
                s_h[(cb + 3) * PLANE + idx] = hv.w;
            }
        }
    }
    __syncthreads();

    // ---- thread mapping: 4 pixels x 16 couts per thread ----
    const int g   = tid & 3;         // channel group: couts {16*gate + 4g + 0..3}
    const int pg  = tid >> 2;        // pixel group 0..127
    const int ty  = pg >> 3;         // 0..15
    const int tx0 = (pg & 7) * 4;    // 0,4,...,28

    // acc[px][j], j = gate*2 + pair; covers couts 16*gate + 4g + 2*pair + {0,1}
    unsigned long long acc[4][8];
    #pragma unroll
    for (int gate = 0; gate < 4; ++gate) {
        #pragma unroll
        for (int pr = 0; pr < 2; ++pr) {
            float2 b2 = *(const float2*)(s_b + gate * 16 + 4 * g + 2 * pr);
            unsigned long long bv = pack2(b2.x, b2.y);
            #pragma unroll
            for (int px = 0; px < 4; ++px) acc[px][gate * 2 + pr] = bv;
        }
    }

    #pragma unroll 1
    for (int cin = 0; cin < CINc; ++cin) {
        const float* xp = s_x + cin * PLANE + ty * SWc + tx0;
        const float* hp = s_h + cin * PLANE + ty * SWc + tx0;
        #pragma unroll
        for (int dy = 0; dy < 3; ++dy) {
            float xr[6], hr[6];
            {
                float4 v4 = *(const float4*)(xp + dy * SWc);
                float2 v2 = *(const float2*)(xp + dy * SWc + 4);
                xr[0] = v4.x; xr[1] = v4.y; xr[2] = v4.z; xr[3] = v4.w;
                xr[4] = v2.x; xr[5] = v2.y;
                if (!FIRST) {
                    float4 w4 = *(const float4*)(hp + dy * SWc);
                    float2 w2 = *(const float2*)(hp + dy * SWc + 4);
                    hr[0] = w4.x; hr[1] = w4.y; hr[2] = w4.z; hr[3] = w4.w;
                    hr[4] = w2.x; hr[5] = w2.y;
                }
            }
            #pragma unroll
            for (int dx = 0; dx < 3; ++dx) {
                const int tap = dy * 3 + dx;
                // x weights: 16 couts for this thread = 4 x LDS.128
                {
                    const float* wb = s_wx + (tap * CINc + cin) * COc + 4 * g;
                    unsigned long long w[8];
                    #pragma unroll
                    for (int gate = 0; gate < 4; ++gate) {
                        ulonglong2 wv = *(const ulonglong2*)(wb + gate * 16);
                        w[gate * 2]     = wv.x;
                        w[gate * 2 + 1] = wv.y;
                    }
                    #pragma unroll
                    for (int px = 0; px < 4; ++px) {
                        const float a = xr[dx + px];
                        const unsigned long long a2 = pack2(a, a);
                        #pragma unroll
                        for (int j = 0; j < 8; ++j) ffma2(acc[px][j], a2, w[j]);
                    }
                }
                if (!FIRST) {
                    const float* wb = s_wh + (tap * CINc + cin) * COc + 4 * g;
                    unsigned long long w[8];
                    #pragma unroll
                    for (int gate = 0; gate < 4; ++gate) {
                        ulonglong2 wv = *(const ulonglong2*)(wb + gate * 16);
                        w[gate * 2]     = wv.x;
                        w[gate * 2 + 1] = wv.y;
                    }
                    #pragma unroll
                    for (int px = 0; px < 4; ++px) {
                        const float a = hr[dx + px];
                        const unsigned long long a2 = pack2(a, a);
                        #pragma unroll
                        for (int j = 0; j < 8; ++j) ffma2(acc[px][j], a2, w[j]);
                    }
                }
            }
        }
    }

    // ---- gate epilogue, per pixel, 4 filters per thread ----
    const int gy = by0 + ty;
    #pragma unroll
    for (int px = 0; px < 4; ++px) {
        float zv[4][4];  // [gate][filter k 0..3]
        #pragma unroll
        for (int gate = 0; gate < 4; ++gate) {
            unpack2(acc[px][gate * 2],     zv[gate][0], zv[gate][1]);
            unpack2(acc[px][gate * 2 + 1], zv[gate][2], zv[gate][3]);
        }
        const int gx = bx0 + tx0 + px;
        const size_t pix = ((size_t)b * (HH * WW) + gy * WW + gx) * FFc + 4 * g;

        float cprev[4] = {0.f, 0.f, 0.f, 0.f};
        if (!FIRST) *(float4*)cprev = *(const float4*)(g_c[rd] + pix);

        float hn[4], cn[4];
        #pragma unroll
        for (int k = 0; k < 4; ++k) {
            const float ig = sigmoidf_(zv[0][k]);
            const float fg = sigmoidf_(zv[1][k]);
            const float zc = zv[2][k];
            const float og = sigmoidf_(zv[3][k]);
            const float c  = fg * cprev[k] + ig * fmaxf(zc, 0.f);
            cn[k] = c;
            hn[k] = og * fmaxf(c, 0.f);
        }

        if (!LAST) {
            *(float4*)(g_c[wi] + pix) = *(const float4*)cn;
            *(float4*)(g_h[wi] + pix) = *(const float4*)hn;
        } else {
            // fused Dense(16->1): partial over this thread's 4 filters,
            // then 4-lane butterfly reduce (lanes g=0..3 of the pixel group)
            float s = hn[0] * dense_w[4 * g + 0] + hn[1] * dense_w[4 * g + 1]
                    + hn[2] * dense_w[4 * g + 2] + hn[3] * dense_w[4 * g + 3];
            s += __shfl_xor_sync(0xFFFFFFFFu, s, 1);
            s += __shfl_xor_sync(0xFFFFFFFFu, s, 2);
            if (g == 0)
                out[(size_t)b * (HH * WW) + gy * WW + gx] = s + dense_b[0];
        }
    }
}

extern "C" void kernel_launch(void* const* d_in, const int* in_sizes, int n_in,
                              void* d_out, int out_size)
{
    const float* x    = (const float*)d_in[0];
    const float* wk   = (const float*)d_in[1];
    const float* wr   = (const float*)d_in[2];
    const float* bias = (const float*)d_in[3];
    const float* dw   = (const float*)d_in[4];
    const float* db   = (const float*)d_in[5];
    float* out = (float*)d_out;

    const int smem_bytes = SMEM_FLOATS * 4;  // ~153 KB
    cudaFuncSetAttribute(convlstm_step<true,  false>,
                         cudaFuncAttributeMaxDynamicSharedMemorySize, smem_bytes);
    cudaFuncSetAttribute(convlstm_step<false, false>,
                         cudaFuncAttributeMaxDynamicSharedMemorySize, smem_bytes);
    cudaFuncSetAttribute(convlstm_step<false, true>,
                         cudaFuncAttributeMaxDynamicSharedMemorySize, smem_bytes);

    dim3 grid(WW / TILE_W, HH / TILE_H, BB);   // (3, 6, 16) = 288 blocks
    dim3 block(512);

    for (int t = 0; t < TT; ++t) {
        const int rd = (t + 1) & 1;   // read buffer
        const int wi = t & 1;         // write buffer
        if (t == 0) {
            convlstm_step<true, false><<<grid, block, smem_bytes>>>(
                x, wk, wr, bias, dw, db, out, t, rd, wi);
        } else if (t == TT - 1) {
            convlstm_step<false, true><<<grid, block, smem_bytes>>>(
                x, wk, wr, bias, dw, db, out, t, rd, wi);
        } else {
            convlstm_step<false, false><<<grid, block, smem_bytes>>>(
                x, wk, wr, bias, dw, db, out, t, rd, wi);
        }
    }
}